// round 3
// baseline (speedup 1.0000x reference)
#include <cuda_runtime.h>
#include <math.h>

#define T_STEPS 16384
#define NNODES  97
#define HID     6

#define NCHUNK  64
#define CHUNK   256
#define WARM    128

// ---------------- scratch (device globals; no runtime allocation) ----------
__device__ float4 g_xp[T_STEPS * NNODES * HID];       // gate pre-activations (i,f,g,o)
__device__ float  g_al[T_STEPS * NNODES * HID];       // LSTM output
__device__ float  g_c1[T_STEPS * 194 * HID];
__device__ float  g_c2[T_STEPS * 194 * HID];
__device__ float  g_c3[T_STEPS * 97 * HID];
__device__ float  g_w1p[97 * 3 * 194];                // packed weights [ci][d][co]
__device__ float  g_w2p[194 * 3 * 194];
__device__ float  g_w3p[194 * 3 * 97];
__device__ float  g_scale[NNODES];
__device__ float  g_shift[NNODES];

__device__ __forceinline__ float sigf(float x) {
    return __fdividef(1.f, 1.f + __expf(-x));
}
__device__ __forceinline__ float tanh_f(float x) {
    float e = __expf(-2.f * fabsf(x));
    return copysignf(__fdividef(1.f - e, 1.f + e), x);
}

// ---------------- K0: pack conv weights (center kw column) -----------------
__global__ void pack_weights(const float* __restrict__ Wc1,
                             const float* __restrict__ Wc2,
                             const float* __restrict__ Wc3) {
    const int n1 = 97 * 3 * 194, n2 = 194 * 3 * 194, n3 = 194 * 3 * 97;
    int i = blockIdx.x * blockDim.x + threadIdx.x;
    if (i < n1) {
        int co = i % 194, rd = i / 194, ci = rd / 3, d = rd % 3;
        g_w1p[i] = Wc1[((co * 97 + ci) * 3 + d) * 3 + 1];
    } else if (i < n1 + n2) {
        int k = i - n1;
        int co = k % 194, rd = k / 194, ci = rd / 3, d = rd % 3;
        g_w2p[k] = Wc2[((co * 194 + ci) * 3 + d) * 3 + 1];
    } else if (i < n1 + n2 + n3) {
        int k = i - n1 - n2;
        int co = k % 97, rd = k / 97, ci = rd / 3, d = rd % 3;
        g_w3p[k] = Wc3[((co * 194 + ci) * 3 + d) * 3 + 1];
    }
}

// ---------------- K1: x-projection, one thread per (t,n) -------------------
__global__ void xproj_kernel(const float* __restrict__ X,
                             const float* __restrict__ Wih,
                             const float* __restrict__ bih,
                             const float* __restrict__ bhh) {
    __shared__ float s_w[288];
    __shared__ float s_b[24];
    for (int i = threadIdx.x; i < 288; i += blockDim.x) s_w[i] = Wih[i];
    if (threadIdx.x < 24) s_b[threadIdx.x] = bih[threadIdx.x] + bhh[threadIdx.x];
    __syncthreads();

    int nt = blockIdx.x * blockDim.x + threadIdx.x;   // t*97 + n
    if (nt >= T_STEPS * NNODES) return;
    const float4* Xv = reinterpret_cast<const float4*>(X) + nt * 3;
    float4 a = __ldg(Xv), b = __ldg(Xv + 1), cc = __ldg(Xv + 2);
    float xv[12] = {a.x, a.y, a.z, a.w, b.x, b.y, b.z, b.w, cc.x, cc.y, cc.z, cc.w};

    float acc[24];
#pragma unroll
    for (int r = 0; r < 24; ++r) {
        float s = s_b[r];
#pragma unroll
        for (int f = 0; f < 12; ++f) s = fmaf(s_w[r * 12 + f], xv[f], s);
        acc[r] = s;
    }
#pragma unroll
    for (int j = 0; j < 6; ++j)
        g_xp[nt * 6 + j] = make_float4(acc[j], acc[6 + j], acc[12 + j], acc[18 + j]);
}

// ---------------- K2: chunked LSTM (5 nodes/warp, shfl h-exchange) ---------
__global__ void lstm_kernel(const float* __restrict__ Whh) {
    int lane = threadIdx.x & 31;
    int w    = threadIdx.x >> 5;
    int g    = lane / 6;
    int j    = lane % 6;
    int node = blockIdx.y * 25 + w * 5 + g;
    bool active = (lane < 30) && (node < NNODES);
    int nn = active ? node : 0;

    float Wr[4][6];
#pragma unroll
    for (int gi = 0; gi < 4; ++gi)
#pragma unroll
        for (int k = 0; k < 6; ++k)
            Wr[gi][k] = __ldg(&Whh[(gi * 6 + j) * 6 + k]);

    float h = 0.f, c = 0.f;
    int t0 = blockIdx.x * CHUNK;
    int tb = t0 - WARM; if (tb < 0) tb = 0;
    int base = g * 6;

    for (int t = tb; t < t0 + CHUNK; ++t) {
        float4 x = __ldg(&g_xp[(t * NNODES + nn) * 6 + j]);
        float hs[6];
#pragma unroll
        for (int k = 0; k < 6; ++k) hs[k] = __shfl_sync(0xffffffffu, h, base + k);
        float gi = x.x, gf = x.y, gg = x.z, go = x.w;
#pragma unroll
        for (int k = 0; k < 6; ++k) {
            gi = fmaf(Wr[0][k], hs[k], gi);
            gf = fmaf(Wr[1][k], hs[k], gf);
            gg = fmaf(Wr[2][k], hs[k], gg);
            go = fmaf(Wr[3][k], hs[k], go);
        }
        float ai = sigf(gi), af = sigf(gf), ag = tanh_f(gg), ao = sigf(go);
        c = fmaf(af, c, ai * ag);
        h = tanh_f(ao * tanh_f(c));
        if (t >= t0 && active) g_al[(t * NNODES + node) * 6 + j] = h;
    }
}

// ---------------- K3: k=3 conv over H=6 + ReLU, tiled ----------------------
// block: 16 t x 64 co, 256 threads; each thread 2t x 2co, acc[2][2][6]
template <int CIN, int COUT>
__global__ void __launch_bounds__(256, 2)
conv_kernel(const float* __restrict__ in, const float* __restrict__ wpk,
            const float* __restrict__ bias, float* __restrict__ out) {
    __shared__ float s_in[32][144];      // [ci][t*9 + hp], hp=0..7 (h=-1..6)
    __shared__ float s_w[32][3][64];     // [ci][d][co]

    int tid = threadIdx.x;
    int cs  = tid & 31;                  // co slot
    int ts  = tid >> 5;                  // t slot 0..7
    int t0  = blockIdx.x * 16;
    int co0 = blockIdx.y * 64;

    // zero pad slots once
    for (int i = tid; i < 32 * 16; i += 256) {
        int ci = i >> 4, t = i & 15;
        s_in[ci][t * 9 + 0] = 0.f;
        s_in[ci][t * 9 + 7] = 0.f;
    }

    float acc[2][2][6];
#pragma unroll
    for (int a = 0; a < 2; ++a)
#pragma unroll
        for (int b = 0; b < 2; ++b)
#pragma unroll
            for (int hh = 0; hh < 6; ++hh) acc[a][b][hh] = 0.f;

    const int NCC = (CIN + 31) / 32;
    for (int ccnk = 0; ccnk < NCC; ++ccnk) {
        __syncthreads();
        // load input tile: 32ci x 16t x 6h
        for (int i = tid; i < 3072; i += 256) {
            int t = i / 192, r = i % 192, ci = r / 6, hh = r % 6;
            int ciG = ccnk * 32 + ci;
            float v = (ciG < CIN) ? __ldg(&in[(t0 + t) * CIN * 6 + ciG * 6 + hh]) : 0.f;
            s_in[ci][t * 9 + hh + 1] = v;
        }
        // load weight tile: 32ci x 3d x 64co
        for (int i = tid; i < 6144; i += 256) {
            int ci = i / 192, r = i % 192, d = r / 64, co = r % 64;
            int ciG = ccnk * 32 + ci, coG = co0 + co;
            float v = (ciG < CIN && coG < COUT) ? __ldg(&wpk[(ciG * 3 + d) * COUT + coG]) : 0.f;
            s_w[ci][d][co] = v;
        }
        __syncthreads();

#pragma unroll 2
        for (int ci = 0; ci < 32; ++ci) {
            float in0[8], in1[8], w0[3], w1[3];
#pragma unroll
            for (int hp = 0; hp < 8; ++hp) {
                in0[hp] = s_in[ci][ts * 9 + hp];
                in1[hp] = s_in[ci][(ts + 8) * 9 + hp];
            }
#pragma unroll
            for (int d = 0; d < 3; ++d) {
                w0[d] = s_w[ci][d][cs];
                w1[d] = s_w[ci][d][cs + 32];
            }
#pragma unroll
            for (int hh = 0; hh < 6; ++hh)
#pragma unroll
                for (int d = 0; d < 3; ++d) {
                    acc[0][0][hh] = fmaf(w0[d], in0[hh + d], acc[0][0][hh]);
                    acc[0][1][hh] = fmaf(w1[d], in0[hh + d], acc[0][1][hh]);
                    acc[1][0][hh] = fmaf(w0[d], in1[hh + d], acc[1][0][hh]);
                    acc[1][1][hh] = fmaf(w1[d], in1[hh + d], acc[1][1][hh]);
                }
        }
    }

    // epilogue: bias + relu + store
#pragma unroll
    for (int b = 0; b < 2; ++b) {
        int co = co0 + cs + b * 32;
        if (co >= COUT) continue;
        float bv = __ldg(&bias[co]);
#pragma unroll
        for (int a = 0; a < 2; ++a) {
            int t = t0 + ts + a * 8;
            float* op = &out[t * COUT * 6 + co * 6];
#pragma unroll
            for (int hh = 0; hh < 6; ++hh)
                op[hh] = fmaxf(acc[a][b][hh] + bv, 0.f);
        }
    }
}

// ---------------- K4: BN batch stats per channel ---------------------------
__global__ void bnstats_kernel(const float* __restrict__ gamma,
                               const float* __restrict__ beta) {
    __shared__ double s_s[256], s_q[256];
    int n = blockIdx.x;
    double s = 0.0, q = 0.0;
    for (int t = threadIdx.x; t < T_STEPS; t += 256) {
        const float* p = &g_c3[(t * 97 + n) * 6];
#pragma unroll
        for (int hh = 0; hh < 6; ++hh) {
            double v = (double)p[hh];
            s += v; q += v * v;
        }
    }
    s_s[threadIdx.x] = s; s_q[threadIdx.x] = q;
    __syncthreads();
    for (int st = 128; st > 0; st >>= 1) {
        if (threadIdx.x < st) {
            s_s[threadIdx.x] += s_s[threadIdx.x + st];
            s_q[threadIdx.x] += s_q[threadIdx.x + st];
        }
        __syncthreads();
    }
    if (threadIdx.x == 0) {
        double N = (double)T_STEPS * 6.0;
        double mean = s_s[0] / N;
        double var = s_q[0] / N - mean * mean;
        float sc = gamma[n] * (float)(1.0 / sqrt(var + 1e-5));
        g_scale[n] = sc;
        g_shift[n] = beta[n] - (float)mean * sc;
    }
}

// ---------------- K5: fused BN apply + linear ------------------------------
__global__ void final_kernel(const float* __restrict__ Wl,
                             const float* __restrict__ bl,
                             float* __restrict__ out) {
    __shared__ float s_wl[36], s_bl[6];
    if (threadIdx.x < 36) s_wl[threadIdx.x] = Wl[threadIdx.x];
    if (threadIdx.x < 6)  s_bl[threadIdx.x] = bl[threadIdx.x];
    __syncthreads();

    int nt = blockIdx.x * blockDim.x + threadIdx.x;
    if (nt >= T_STEPS * NNODES) return;
    int n = nt % NNODES;
    float sc = __ldg(&g_scale[n]), sh = __ldg(&g_shift[n]);
    const float* p = &g_c3[nt * 6];
    float v[6];
#pragma unroll
    for (int hh = 0; hh < 6; ++hh) v[hh] = fmaf(p[hh], sc, sh);
#pragma unroll
    for (int j = 0; j < 6; ++j) {
        float o = s_bl[j];
#pragma unroll
        for (int hh = 0; hh < 6; ++hh) o = fmaf(v[hh], s_wl[j * 6 + hh], o);
        out[nt * 6 + j] = o;
    }
}

// ---------------- launch ----------------------------------------------------
extern "C" void kernel_launch(void* const* d_in, const int* in_sizes, int n_in,
                              void* d_out, int out_size) {
    const float* X    = (const float*)d_in[1];
    const float* Wih  = (const float*)d_in[3];
    const float* Whh  = (const float*)d_in[4];
    const float* bih  = (const float*)d_in[5];
    const float* bhh  = (const float*)d_in[6];
    const float* Wc1  = (const float*)d_in[7];
    const float* bc1  = (const float*)d_in[8];
    const float* Wc2  = (const float*)d_in[9];
    const float* bc2  = (const float*)d_in[10];
    const float* Wc3  = (const float*)d_in[11];
    const float* bc3  = (const float*)d_in[12];
    const float* gamma = (const float*)d_in[13];
    const float* beta  = (const float*)d_in[14];
    const float* Wl   = (const float*)d_in[15];
    const float* bl   = (const float*)d_in[16];
    float* out = (float*)d_out;

    float *al, *c1, *c2, *c3, *w1p, *w2p, *w3p;
    cudaGetSymbolAddress((void**)&al,  g_al);
    cudaGetSymbolAddress((void**)&c1,  g_c1);
    cudaGetSymbolAddress((void**)&c2,  g_c2);
    cudaGetSymbolAddress((void**)&c3,  g_c3);
    cudaGetSymbolAddress((void**)&w1p, g_w1p);
    cudaGetSymbolAddress((void**)&w2p, g_w2p);
    cudaGetSymbolAddress((void**)&w3p, g_w3p);

    pack_weights<<<883, 256>>>(Wc1, Wc2, Wc3);
    xproj_kernel<<<(T_STEPS * NNODES + 255) / 256, 256>>>(X, Wih, bih, bhh);
    lstm_kernel<<<dim3(NCHUNK, 4), 160>>>(Whh);
    conv_kernel<97, 194><<<dim3(T_STEPS / 16, 4), 256>>>(al, w1p, bc1, c1);
    conv_kernel<194, 194><<<dim3(T_STEPS / 16, 4), 256>>>(c1, w2p, bc2, c2);
    conv_kernel<194, 97><<<dim3(T_STEPS / 16, 2), 256>>>(c2, w3p, bc3, c3);
    bnstats_kernel<<<97, 256>>>(gamma, beta);
    final_kernel<<<(T_STEPS * NNODES + 255) / 256, 256>>>(Wl, bl, out);
}

// round 5
// speedup vs baseline: 1.6256x; 1.6256x over previous
#include <cuda_runtime.h>
#include <cuda_bf16.h>
#include <math.h>
#include <stdint.h>

#define T_STEPS 16384
#define NNODES  97
#define HID     6
#define ROWS_PAD (T_STEPS * 8)     // 131072 padded rows (8 h-slots per t)

#define NCHUNK  64
#define CHUNK   256
#define WARM    128

#define K1   112                    // conv1 K: 97 ci -> pad 112 (7 k16 chunks)
#define K23  208                    // conv2/3 K: 194 -> pad 208 (13 chunks)

// ---------------- scratch (device globals; zero-initialized .bss) ----------
// Pad slots (hp=0,7), pad K columns, and guard reads rely on zero init and
// are NEVER written -> stay zero across graph replays.
__device__ float4 g_xp[T_STEPS * NNODES * HID];
__device__ unsigned short g_R1h[(size_t)ROWS_PAD * K1];
__device__ unsigned short g_R1l[(size_t)ROWS_PAD * K1];
__device__ unsigned short g_R2h[(size_t)ROWS_PAD * K23];
__device__ unsigned short g_R2l[(size_t)ROWS_PAD * K23];
__device__ unsigned short g_R3h[(size_t)ROWS_PAD * K23];
__device__ unsigned short g_R3l[(size_t)ROWS_PAD * K23];
__device__ float g_c3[(size_t)T_STEPS * 582];
__device__ unsigned int g_B1[7  * 26 * 384];   // [kc][nf][tap][split][lane][reg]
__device__ unsigned int g_B2[13 * 26 * 384];
__device__ unsigned int g_B3[13 * 13 * 384];
__device__ float g_scale[NNODES];
__device__ float g_shift[NNODES];

// ---------------- helpers ---------------------------------------------------
__device__ __forceinline__ float sigf(float x) {
    return __fdividef(1.f, 1.f + __expf(-x));
}
__device__ __forceinline__ float tanh_f(float x) {
    float e = __expf(-2.f * fabsf(x));
    return copysignf(__fdividef(1.f - e, 1.f + e), x);
}
__device__ __forceinline__ uint32_t smem_u32(const void* p) {
    uint32_t a;
    asm("{ .reg .u64 t; cvta.to.shared.u64 t, %1; cvt.u32.u64 %0, t; }" : "=r"(a) : "l"(p));
    return a;
}
__device__ __forceinline__ unsigned short bf16_bits(float v) {
    __nv_bfloat16 b = __float2bfloat16(v);
    return *reinterpret_cast<unsigned short*>(&b);
}
__device__ __forceinline__ float bf16_val(unsigned short u) {
    __nv_bfloat16 b = *reinterpret_cast<__nv_bfloat16*>(&u);
    return __bfloat162float(b);
}
__device__ __forceinline__ void ldmx4(uint32_t* r, uint32_t addr) {
    asm volatile("ldmatrix.sync.aligned.m8n8.x4.shared.b16 {%0,%1,%2,%3}, [%4];"
                 : "=r"(r[0]), "=r"(r[1]), "=r"(r[2]), "=r"(r[3]) : "r"(addr));
}
__device__ __forceinline__ void mma_bf16(float* d, const uint32_t* a, uint32_t b0, uint32_t b1) {
    asm volatile(
        "mma.sync.aligned.m16n8k16.row.col.f32.bf16.bf16.f32 "
        "{%0,%1,%2,%3}, {%4,%5,%6,%7}, {%8,%9}, {%0,%1,%2,%3};"
        : "+f"(d[0]), "+f"(d[1]), "+f"(d[2]), "+f"(d[3])
        : "r"(a[0]), "r"(a[1]), "r"(a[2]), "r"(a[3]), "r"(b0), "r"(b1));
}

// ---------------- K0: pack tap weights into mma B-fragment layout -----------
// b32 at [kc][nf][tap][split][lane][reg] holds B[k][n],B[k+1][n] as bf16x2,
// where B[k=ci][n=co] = W[co][ci][tap][kw=1]; split0 = hi, split1 = residual.
__global__ void pack_B(const float* __restrict__ Wc1,
                       const float* __restrict__ Wc2,
                       const float* __restrict__ Wc3) {
    const int N1 = 7 * 26 * 384, N2 = 13 * 26 * 384, N3 = 13 * 13 * 384;
    int idx = blockIdx.x * 256 + threadIdx.x;
    const float* W; unsigned int* dst; int NFALL, CIN, COUT, li;
    if (idx < N1)           { W = Wc1; dst = g_B1; NFALL = 26; CIN = 97;  COUT = 194; li = idx; }
    else if (idx < N1 + N2) { W = Wc2; dst = g_B2; NFALL = 26; CIN = 194; COUT = 194; li = idx - N1; }
    else if (idx < N1 + N2 + N3) { W = Wc3; dst = g_B3; NFALL = 13; CIN = 194; COUT = 97; li = idx - N1 - N2; }
    else return;

    int reg   = li & 1;
    int lane  = (li >> 1) & 31;
    int split = (li >> 6) & 1;
    int tap   = (li / 128) % 3;
    int nf    = (li / 384) % NFALL;
    int kc    = li / (384 * NFALL);

    int n  = nf * 8 + (lane >> 2);
    int k0 = kc * 16 + (lane & 3) * 2 + reg * 8;
    float w0 = 0.f, w1 = 0.f;
    if (n < COUT) {
        if (k0 < CIN)     w0 = W[((n * CIN + k0) * 3 + tap) * 3 + 1];
        if (k0 + 1 < CIN) w1 = W[((n * CIN + k0 + 1) * 3 + tap) * 3 + 1];
    }
    unsigned short h0, h1;
    if (split == 0) { h0 = bf16_bits(w0); h1 = bf16_bits(w1); }
    else {
        h0 = bf16_bits(w0 - bf16_val(bf16_bits(w0)));
        h1 = bf16_bits(w1 - bf16_val(bf16_bits(w1)));
    }
    dst[li] = (unsigned int)h0 | ((unsigned int)h1 << 16);
}

// ---------------- K1: x-projection ------------------------------------------
__global__ void xproj_kernel(const float* __restrict__ X,
                             const float* __restrict__ Wih,
                             const float* __restrict__ bih,
                             const float* __restrict__ bhh) {
    __shared__ float s_w[288];
    __shared__ float s_b[24];
    for (int i = threadIdx.x; i < 288; i += blockDim.x) s_w[i] = Wih[i];
    if (threadIdx.x < 24) s_b[threadIdx.x] = bih[threadIdx.x] + bhh[threadIdx.x];
    __syncthreads();

    int nt = blockIdx.x * blockDim.x + threadIdx.x;
    if (nt >= T_STEPS * NNODES) return;
    const float4* Xv = reinterpret_cast<const float4*>(X) + nt * 3;
    float4 a = __ldg(Xv), b = __ldg(Xv + 1), cc = __ldg(Xv + 2);
    float xv[12] = {a.x, a.y, a.z, a.w, b.x, b.y, b.z, b.w, cc.x, cc.y, cc.z, cc.w};

    float acc[24];
#pragma unroll
    for (int r = 0; r < 24; ++r) {
        float s = s_b[r];
#pragma unroll
        for (int f = 0; f < 12; ++f) s = fmaf(s_w[r * 12 + f], xv[f], s);
        acc[r] = s;
    }
#pragma unroll
    for (int j = 0; j < 6; ++j)
        g_xp[nt * 6 + j] = make_float4(acc[j], acc[6 + j], acc[12 + j], acc[18 + j]);
}

// ---------------- K2: chunked LSTM (contractive-restart parallelization) ----
__global__ void lstm_kernel(const float* __restrict__ Whh,
                            unsigned short* __restrict__ R1h,
                            unsigned short* __restrict__ R1l) {
    int lane = threadIdx.x & 31;
    int w    = threadIdx.x >> 5;
    int g    = lane / 6;
    int j    = lane % 6;
    int node = blockIdx.y * 25 + w * 5 + g;
    bool active = (lane < 30) && (node < NNODES);
    int nn = active ? node : 0;

    float Wr[4][6];
#pragma unroll
    for (int gi = 0; gi < 4; ++gi)
#pragma unroll
        for (int k = 0; k < 6; ++k)
            Wr[gi][k] = __ldg(&Whh[(gi * 6 + j) * 6 + k]);

    float h = 0.f, c = 0.f;
    int t0 = blockIdx.x * CHUNK;
    int tb = t0 - WARM; if (tb < 0) tb = 0;
    int base = g * 6;

    for (int t = tb; t < t0 + CHUNK; ++t) {
        float4 x = __ldg(&g_xp[(t * NNODES + nn) * 6 + j]);
        float hs[6];
#pragma unroll
        for (int k = 0; k < 6; ++k) hs[k] = __shfl_sync(0xffffffffu, h, base + k);
        float gi = x.x, gf = x.y, gg = x.z, go = x.w;
#pragma unroll
        for (int k = 0; k < 6; ++k) {
            gi = fmaf(Wr[0][k], hs[k], gi);
            gf = fmaf(Wr[1][k], hs[k], gf);
            gg = fmaf(Wr[2][k], hs[k], gg);
            go = fmaf(Wr[3][k], hs[k], go);
        }
        float ai = sigf(gi), af = sigf(gf), ag = tanh_f(gg), ao = sigf(go);
        c = fmaf(af, c, ai * ag);
        h = tanh_f(ao * tanh_f(c));
        if (t >= t0 && active) {
            // padded row = t*8 + (h-slot = j+1); column = node (K index of conv1)
            size_t p = ((size_t)t * 8 + j + 1) * K1 + node;
            unsigned short hb = bf16_bits(h);
            R1h[p] = hb;
            R1l[p] = bf16_bits(h - bf16_val(hb));
        }
    }
}

// ---------------- K3: tap-decomposed conv GEMM via mma.sync bf16 ------------
// CTA tile: M=256 padded rows x N=104 cols. 8 warps, each m32 (2 m-frags).
// Per k16 chunk: load A rows [m0-1, m0+257) hi/lo + B fragment slice, then
// 3 taps x 3 split-terms x 13 n-frags x 2 m-frags MMAs.
template <int KPAD, int COUT, int NFALL, int ONPAD, bool LAST>
__global__ void __launch_bounds__(256)
conv_mma(const unsigned short* __restrict__ Rh, const unsigned short* __restrict__ Rl,
         const unsigned int* __restrict__ Bpk, const float* __restrict__ bias,
         unsigned short* __restrict__ Oh, unsigned short* __restrict__ Ol,
         float* __restrict__ Oc) {
    __shared__ unsigned int sA[2][258 * 12];   // 48B row stride (12 words), conflict-free ldmatrix
    __shared__ unsigned int sB[4992];          // 13 nf x 3 tap x 2 split x 64

    const int tid = threadIdx.x, warp = tid >> 5, lane = tid & 31;
    const int m0  = blockIdx.x * 256;
    const int co0 = blockIdx.y * 104;
    const uint32_t aBase = smem_u32(sA);

    float acc[2][13][4];
#pragma unroll
    for (int mf = 0; mf < 2; ++mf)
#pragma unroll
        for (int nf = 0; nf < 13; ++nf)
#pragma unroll
            for (int j = 0; j < 4; ++j) acc[mf][nf][j] = 0.f;

    const int NK = KPAD / 16;
    for (int kc = 0; kc < NK; ++kc) {
        __syncthreads();
        // A tile: 258 rows x 16 bf16 (8 b32), hi + lo
        for (int i = tid; i < 258 * 8; i += 256) {
            int row = i >> 3, q = i & 7;
            int r = m0 - 1 + row;
            unsigned int vh = 0, vl = 0;
            if (r >= 0 && r < ROWS_PAD) {
                size_t wi = (((size_t)r * KPAD + kc * 16) >> 1) + q;
                vh = reinterpret_cast<const unsigned int*>(Rh)[wi];
                vl = reinterpret_cast<const unsigned int*>(Rl)[wi];
            }
            sA[0][row * 12 + q] = vh;
            sA[1][row * 12 + q] = vl;
        }
        // B slice for this kc and this CTA's 13 n-frags (contiguous)
        const unsigned int* bsrc = Bpk + ((size_t)kc * NFALL + blockIdx.y * 13) * 384;
        for (int i = tid; i < 4992; i += 256) sB[i] = bsrc[i];
        __syncthreads();

        uint32_t ah[3][2][4], al[3][2][4];
#pragma unroll
        for (int tap = 0; tap < 3; ++tap)
#pragma unroll
            for (int mf = 0; mf < 2; ++mf) {
                int rowb = warp * 32 + mf * 16 + tap + (lane & 15);
                uint32_t ad = aBase + (unsigned)(rowb * 12 + (lane >> 4) * 4) * 4u;
                ldmx4(ah[tap][mf], ad);
                ldmx4(al[tap][mf], ad + 258 * 12 * 4);
            }
#pragma unroll
        for (int nf = 0; nf < 13; ++nf)
#pragma unroll
            for (int tap = 0; tap < 3; ++tap) {
                uint2 bh = *reinterpret_cast<const uint2*>(&sB[((nf * 3 + tap) * 2 + 0) * 64 + lane * 2]);
                uint2 bl = *reinterpret_cast<const uint2*>(&sB[((nf * 3 + tap) * 2 + 1) * 64 + lane * 2]);
#pragma unroll
                for (int mf = 0; mf < 2; ++mf) {
                    mma_bf16(acc[mf][nf], ah[tap][mf], bh.x, bh.y);
                    mma_bf16(acc[mf][nf], al[tap][mf], bh.x, bh.y);
                    mma_bf16(acc[mf][nf], ah[tap][mf], bl.x, bl.y);
                }
            }
    }

    // epilogue: bias + relu; keep only h-slots 1..6 and co < COUT
#pragma unroll
    for (int mf = 0; mf < 2; ++mf)
#pragma unroll
        for (int nf = 0; nf < 13; ++nf)
#pragma unroll
            for (int j = 0; j < 4; ++j) {
                int row = warp * 32 + mf * 16 + (lane >> 2) + (j >> 1) * 8;
                int o = m0 + row, slot = o & 7;
                int n = nf * 8 + (lane & 3) * 2 + (j & 1);
                int co = co0 + n;
                if (slot >= 1 && slot <= 6 && co < COUT) {
                    float v = fmaxf(acc[mf][nf][j] + __ldg(&bias[co]), 0.f);
                    if (LAST) {
                        Oc[(size_t)(o >> 3) * 582 + co * 6 + (slot - 1)] = v;
                    } else {
                        unsigned short hb = bf16_bits(v);
                        size_t p = (size_t)o * ONPAD + co;
                        Oh[p] = hb;
                        Ol[p] = bf16_bits(v - bf16_val(hb));
                    }
                }
            }
}

// ---------------- K4: BN batch stats per channel ---------------------------
__global__ void bnstats_kernel(const float* __restrict__ gamma,
                               const float* __restrict__ beta) {
    __shared__ double s_s[256], s_q[256];
    int n = blockIdx.x;
    double s = 0.0, q = 0.0;
    for (int t = threadIdx.x; t < T_STEPS; t += 256) {
        const float* p = &g_c3[(size_t)t * 582 + n * 6];
#pragma unroll
        for (int hh = 0; hh < 6; ++hh) {
            double v = (double)p[hh];
            s += v; q += v * v;
        }
    }
    s_s[threadIdx.x] = s; s_q[threadIdx.x] = q;
    __syncthreads();
    for (int st = 128; st > 0; st >>= 1) {
        if (threadIdx.x < st) {
            s_s[threadIdx.x] += s_s[threadIdx.x + st];
            s_q[threadIdx.x] += s_q[threadIdx.x + st];
        }
        __syncthreads();
    }
    if (threadIdx.x == 0) {
        double N = (double)T_STEPS * 6.0;
        double mean = s_s[0] / N;
        double var = s_q[0] / N - mean * mean;
        float sc = gamma[n] * (float)(1.0 / sqrt(var + 1e-5));
        g_scale[n] = sc;
        g_shift[n] = beta[n] - (float)mean * sc;
    }
}

// ---------------- K5: fused BN apply + linear ------------------------------
__global__ void final_kernel(const float* __restrict__ Wl,
                             const float* __restrict__ bl,
                             float* __restrict__ out) {
    __shared__ float s_wl[36], s_bl[6];
    if (threadIdx.x < 36) s_wl[threadIdx.x] = Wl[threadIdx.x];
    if (threadIdx.x < 6)  s_bl[threadIdx.x] = bl[threadIdx.x];
    __syncthreads();

    int nt = blockIdx.x * blockDim.x + threadIdx.x;
    if (nt >= T_STEPS * NNODES) return;
    int n = nt % NNODES;
    float sc = __ldg(&g_scale[n]), sh = __ldg(&g_shift[n]);
    const float* p = &g_c3[(size_t)nt * 6];
    float v[6];
#pragma unroll
    for (int hh = 0; hh < 6; ++hh) v[hh] = fmaf(p[hh], sc, sh);
#pragma unroll
    for (int j = 0; j < 6; ++j) {
        float o = s_bl[j];
#pragma unroll
        for (int hh = 0; hh < 6; ++hh) o = fmaf(v[hh], s_wl[j * 6 + hh], o);
        out[nt * 6 + j] = o;
    }
}

// ---------------- launch ----------------------------------------------------
extern "C" void kernel_launch(void* const* d_in, const int* in_sizes, int n_in,
                              void* d_out, int out_size) {
    const float* X    = (const float*)d_in[1];
    const float* Wih  = (const float*)d_in[3];
    const float* Whh  = (const float*)d_in[4];
    const float* bih  = (const float*)d_in[5];
    const float* bhh  = (const float*)d_in[6];
    const float* Wc1  = (const float*)d_in[7];
    const float* bc1  = (const float*)d_in[8];
    const float* Wc2  = (const float*)d_in[9];
    const float* bc2  = (const float*)d_in[10];
    const float* Wc3  = (const float*)d_in[11];
    const float* bc3  = (const float*)d_in[12];
    const float* gamma = (const float*)d_in[13];
    const float* beta  = (const float*)d_in[14];
    const float* Wl   = (const float*)d_in[15];
    const float* bl   = (const float*)d_in[16];
    float* out = (float*)d_out;

    unsigned short *r1h, *r1l, *r2h, *r2l, *r3h, *r3l;
    unsigned int *b1, *b2, *b3;
    float* c3;
    cudaGetSymbolAddress((void**)&r1h, g_R1h);
    cudaGetSymbolAddress((void**)&r1l, g_R1l);
    cudaGetSymbolAddress((void**)&r2h, g_R2h);
    cudaGetSymbolAddress((void**)&r2l, g_R2l);
    cudaGetSymbolAddress((void**)&r3h, g_R3h);
    cudaGetSymbolAddress((void**)&r3l, g_R3l);
    cudaGetSymbolAddress((void**)&b1, g_B1);
    cudaGetSymbolAddress((void**)&b2, g_B2);
    cudaGetSymbolAddress((void**)&b3, g_B3);
    cudaGetSymbolAddress((void**)&c3, g_c3);

    const int NPACK = 7 * 26 * 384 + 13 * 26 * 384 + 13 * 13 * 384;
    pack_B<<<(NPACK + 255) / 256, 256>>>(Wc1, Wc2, Wc3);
    xproj_kernel<<<(T_STEPS * NNODES + 255) / 256, 256>>>(X, Wih, bih, bhh);
    lstm_kernel<<<dim3(NCHUNK, 4), 160>>>(Whh, r1h, r1l);
    conv_mma<K1, 194, 26, K23, false><<<dim3(512, 2), 256>>>(r1h, r1l, b1, bc1, r2h, r2l, nullptr);
    conv_mma<K23, 194, 26, K23, false><<<dim3(512, 2), 256>>>(r2h, r2l, b2, bc2, r3h, r3l, nullptr);
    conv_mma<K23, 97, 13, K23, true><<<dim3(512, 1), 256>>>(r3h, r3l, b3, bc3, nullptr, nullptr, c3);
    bnstats_kernel<<<97, 256>>>(gamma, beta);
    final_kernel<<<(T_STEPS * NNODES + 255) / 256, 256>>>(Wl, bl, out);
}

// round 6
// speedup vs baseline: 2.3595x; 1.4515x over previous
#include <cuda_runtime.h>
#include <cuda_bf16.h>
#include <math.h>
#include <stdint.h>

#define T_STEPS 16384
#define NNODES  97
#define HID     6
#define ROWS_PAD (T_STEPS * 8)     // 131072 padded rows (8 h-slots per t)

#define NCHUNK  64
#define CHUNK   256
#define WARM    128

#define K1   112                    // conv1 K: 97 ci -> pad 112 (7 k16 chunks)
#define K23  208                    // conv2/3 K: 194 -> pad 208 (13 chunks)

// smem word offsets for conv kernel (dynamic smem)
#define SA_WORDS_PER  1560          // 130 rows * 12 words
#define OFF_B         6240          // 2 buf * 2 split * 1560
#define OFF_BIAS      16224         // 6240 + 2*4992
#define CONV_SMEM_B   65312        // bytes: (16224 + 104) * 4

// ---------------- scratch (device globals; zero-initialized .bss) ----------
__device__ unsigned short g_R1h[(size_t)ROWS_PAD * K1];
__device__ unsigned short g_R1l[(size_t)ROWS_PAD * K1];
__device__ unsigned short g_R2h[(size_t)ROWS_PAD * K23];
__device__ unsigned short g_R2l[(size_t)ROWS_PAD * K23];
__device__ unsigned short g_R3h[(size_t)ROWS_PAD * K23];
__device__ unsigned short g_R3l[(size_t)ROWS_PAD * K23];
__device__ float g_c3[(size_t)T_STEPS * 582];
__device__ unsigned int g_B1[7  * 26 * 384];   // [kc][nf][tap][split][lane][reg]
__device__ unsigned int g_B2[13 * 26 * 384];
__device__ unsigned int g_B3[13 * 13 * 384];
__device__ float g_scale[NNODES];
__device__ float g_shift[NNODES];

// ---------------- helpers ---------------------------------------------------
__device__ __forceinline__ float sigf(float x) {
    return __fdividef(1.f, 1.f + __expf(-x));
}
__device__ __forceinline__ float tanh_f(float x) {
    float e = __expf(-2.f * fabsf(x));
    return copysignf(__fdividef(1.f - e, 1.f + e), x);
}
__device__ __forceinline__ uint32_t smem_u32(const void* p) {
    uint32_t a;
    asm("{ .reg .u64 t; cvta.to.shared.u64 t, %1; cvt.u32.u64 %0, t; }" : "=r"(a) : "l"(p));
    return a;
}
__device__ __forceinline__ uint64_t gptr(const void* p) {
    uint64_t g;
    asm("cvta.to.global.u64 %0, %1;" : "=l"(g) : "l"(p));
    return g;
}
__device__ __forceinline__ unsigned short bf16_bits(float v) {
    __nv_bfloat16 b = __float2bfloat16(v);
    return *reinterpret_cast<unsigned short*>(&b);
}
__device__ __forceinline__ float bf16_val(unsigned short u) {
    __nv_bfloat16 b = *reinterpret_cast<__nv_bfloat16*>(&u);
    return __bfloat162float(b);
}
__device__ __forceinline__ void ldmx4(uint32_t* r, uint32_t addr) {
    asm volatile("ldmatrix.sync.aligned.m8n8.x4.shared.b16 {%0,%1,%2,%3}, [%4];"
                 : "=r"(r[0]), "=r"(r[1]), "=r"(r[2]), "=r"(r[3]) : "r"(addr));
}
__device__ __forceinline__ void mma_bf16(float* d, const uint32_t* a, uint32_t b0, uint32_t b1) {
    asm volatile(
        "mma.sync.aligned.m16n8k16.row.col.f32.bf16.bf16.f32 "
        "{%0,%1,%2,%3}, {%4,%5,%6,%7}, {%8,%9}, {%0,%1,%2,%3};"
        : "+f"(d[0]), "+f"(d[1]), "+f"(d[2]), "+f"(d[3])
        : "r"(a[0]), "r"(a[1]), "r"(a[2]), "r"(a[3]), "r"(b0), "r"(b1));
}
template <int N>
__device__ __forceinline__ void cp_wait() {
    asm volatile("cp.async.wait_group %0;" :: "n"(N) : "memory");
}

// ---------------- K0: pack tap weights into mma B-fragment layout -----------
__global__ void pack_B(const float* __restrict__ Wc1,
                       const float* __restrict__ Wc2,
                       const float* __restrict__ Wc3) {
    const int N1 = 7 * 26 * 384, N2 = 13 * 26 * 384, N3 = 13 * 13 * 384;
    int idx = blockIdx.x * 256 + threadIdx.x;
    const float* W; unsigned int* dst; int NFALL, CIN, COUT, li;
    if (idx < N1)           { W = Wc1; dst = g_B1; NFALL = 26; CIN = 97;  COUT = 194; li = idx; }
    else if (idx < N1 + N2) { W = Wc2; dst = g_B2; NFALL = 26; CIN = 194; COUT = 194; li = idx - N1; }
    else if (idx < N1 + N2 + N3) { W = Wc3; dst = g_B3; NFALL = 13; CIN = 194; COUT = 97; li = idx - N1 - N2; }
    else return;

    int reg   = li & 1;
    int lane  = (li >> 1) & 31;
    int split = (li >> 6) & 1;
    int tap   = (li / 128) % 3;
    int nf    = (li / 384) % NFALL;
    int kc    = li / (384 * NFALL);

    int n  = nf * 8 + (lane >> 2);
    int k0 = kc * 16 + (lane & 3) * 2 + reg * 8;
    float w0 = 0.f, w1 = 0.f;
    if (n < COUT) {
        if (k0 < CIN)     w0 = W[((n * CIN + k0) * 3 + tap) * 3 + 1];
        if (k0 + 1 < CIN) w1 = W[((n * CIN + k0 + 1) * 3 + tap) * 3 + 1];
    }
    unsigned short h0, h1;
    if (split == 0) { h0 = bf16_bits(w0); h1 = bf16_bits(w1); }
    else {
        h0 = bf16_bits(w0 - bf16_val(bf16_bits(w0)));
        h1 = bf16_bits(w1 - bf16_val(bf16_bits(w1)));
    }
    dst[li] = (unsigned int)h0 | ((unsigned int)h1 << 16);
}

// ---------------- K1: fused x-projection + chunked LSTM ---------------------
// Lane = (node-slot g, unit j); 5 nodes/warp. Each lane loads an 8B X slice,
// 12 shfl broadcasts rebuild the node's 12 inputs; x-proj has no h-dependence
// so it overlaps the recurrence latency.
__global__ void lstm_kernel(const float* __restrict__ X,
                            const float* __restrict__ Wih,
                            const float* __restrict__ bih,
                            const float* __restrict__ bhh,
                            const float* __restrict__ Whh,
                            unsigned short* __restrict__ R1h,
                            unsigned short* __restrict__ R1l) {
    int lane = threadIdx.x & 31;
    int w    = threadIdx.x >> 5;
    int g    = lane / 6;
    int j    = lane % 6;
    int node = blockIdx.y * 25 + w * 5 + g;
    bool active = (lane < 30) && (node < NNODES);
    int nn = active ? node : 0;

    float Wx[4][12], Wr[4][6], bsum[4];
#pragma unroll
    for (int gi = 0; gi < 4; ++gi) {
        int row = gi * 6 + j;
        bsum[gi] = __ldg(&bih[row]) + __ldg(&bhh[row]);
#pragma unroll
        for (int f = 0; f < 12; ++f) Wx[gi][f] = __ldg(&Wih[row * 12 + f]);
#pragma unroll
        for (int k = 0; k < 6; ++k)  Wr[gi][k] = __ldg(&Whh[row * 6 + k]);
    }

    float h = 0.f, c = 0.f;
    int t0 = blockIdx.x * CHUNK;
    int tb = t0 - WARM; if (tb < 0) tb = 0;
    int base = g * 6;

    for (int t = tb; t < t0 + CHUNK; ++t) {
        float2 xp = __ldg(reinterpret_cast<const float2*>(
            X + ((size_t)t * NNODES + nn) * 12 + 2 * j));
        float xv[12];
#pragma unroll
        for (int m = 0; m < 6; ++m) {
            xv[2 * m]     = __shfl_sync(0xffffffffu, xp.x, base + m);
            xv[2 * m + 1] = __shfl_sync(0xffffffffu, xp.y, base + m);
        }
        float gate[4];
#pragma unroll
        for (int gi = 0; gi < 4; ++gi) {
            float s = bsum[gi];
#pragma unroll
            for (int f = 0; f < 12; ++f) s = fmaf(Wx[gi][f], xv[f], s);
            gate[gi] = s;
        }
        float hs[6];
#pragma unroll
        for (int k = 0; k < 6; ++k) hs[k] = __shfl_sync(0xffffffffu, h, base + k);
#pragma unroll
        for (int k = 0; k < 6; ++k) {
            gate[0] = fmaf(Wr[0][k], hs[k], gate[0]);
            gate[1] = fmaf(Wr[1][k], hs[k], gate[1]);
            gate[2] = fmaf(Wr[2][k], hs[k], gate[2]);
            gate[3] = fmaf(Wr[3][k], hs[k], gate[3]);
        }
        float ai = sigf(gate[0]), af = sigf(gate[1]);
        float ag = tanh_f(gate[2]), ao = sigf(gate[3]);
        c = fmaf(af, c, ai * ag);
        h = tanh_f(ao * tanh_f(c));
        if (t >= t0 && active) {
            size_t p = ((size_t)t * 8 + j + 1) * K1 + node;
            unsigned short hb = bf16_bits(h);
            R1h[p] = hb;
            R1l[p] = bf16_bits(h - bf16_val(hb));
        }
    }
}

// ---------------- conv tile prefetch via cp.async ---------------------------
template <int KPAD, int NFALL>
__device__ __forceinline__ void conv_prefetch(
    const unsigned short* Rh, const unsigned short* Rl,
    const unsigned int* Bpk, int m0, int ycol, int kc, int buf,
    int tid, uint32_t sbase) {
    // A tile: 130 rows x (2 splits x 2 halves of 16B)
#pragma unroll 1
    for (int i = tid; i < 520; i += 256) {
        int row = i >> 2, sub = i & 3;
        int split = sub >> 1, half = sub & 1;
        int r = m0 - 1 + row;
        int ok = (r >= 0 && r < ROWS_PAD);
        int rc = ok ? r : 0;
        const unsigned short* src = (split ? Rl : Rh) +
            (size_t)rc * KPAD + kc * 16 + half * 8;
        uint32_t dst = sbase +
            (uint32_t)(((buf * 2 + split) * SA_WORDS_PER + row * 12 + half * 4) * 4);
        unsigned sz = ok ? 16u : 0u;
        asm volatile("cp.async.cg.shared.global [%0], [%1], 16, %2;"
                     :: "r"(dst), "l"(gptr(src)), "r"(sz) : "memory");
    }
    // B slice: 13 nf x 384 words
    const unsigned int* bsrc = Bpk + ((size_t)kc * NFALL + ycol * 13) * 384;
#pragma unroll 1
    for (int i = tid; i < 1248; i += 256) {
        uint32_t dst = sbase + (uint32_t)((OFF_B + buf * 4992 + i * 4) * 4);
        asm volatile("cp.async.cg.shared.global [%0], [%1], 16, %2;"
                     :: "r"(dst), "l"(gptr(bsrc + i * 4)), "r"(16u) : "memory");
    }
    asm volatile("cp.async.commit_group;" ::: "memory");
}

// ---------------- K3: tap-decomposed conv GEMM, double-buffered -------------
// CTA tile: M=128 rows x N=104 cols; 8 warps x m16; 2-stage cp.async pipeline.
template <int KPAD, int COUT, int NFALL, int ONPAD, bool LAST>
__global__ void __launch_bounds__(256, 2)
conv_mma(const unsigned short* __restrict__ Rh, const unsigned short* __restrict__ Rl,
         const unsigned int* __restrict__ Bpk, const float* __restrict__ bias,
         unsigned short* __restrict__ Oh, unsigned short* __restrict__ Ol,
         float* __restrict__ Oc) {
    extern __shared__ unsigned int smw[];
    const uint32_t sbase = smem_u32(smw);
    float* s_bias = reinterpret_cast<float*>(smw + OFF_BIAS);

    const int tid = threadIdx.x, warp = tid >> 5, lane = tid & 31;
    const int m0  = blockIdx.x * 128;
    const int co0 = blockIdx.y * 104;
    if (tid < 104) s_bias[tid] = (co0 + tid < COUT) ? __ldg(&bias[co0 + tid]) : 0.f;

    float acc[13][4];
#pragma unroll
    for (int nf = 0; nf < 13; ++nf)
#pragma unroll
        for (int j = 0; j < 4; ++j) acc[nf][j] = 0.f;

    const int NK = KPAD / 16;
    conv_prefetch<KPAD, NFALL>(Rh, Rl, Bpk, m0, blockIdx.y, 0, 0, tid, sbase);

    for (int kc = 0; kc < NK; ++kc) {
        if (kc + 1 < NK) {
            conv_prefetch<KPAD, NFALL>(Rh, Rl, Bpk, m0, blockIdx.y,
                                       kc + 1, (kc + 1) & 1, tid, sbase);
            cp_wait<1>();
        } else {
            cp_wait<0>();
        }
        __syncthreads();
        const int b = kc & 1;

        uint32_t ah[3][4], al[3][4];
#pragma unroll
        for (int tap = 0; tap < 3; ++tap) {
            int rowb = warp * 16 + tap + (lane & 15);
            uint32_t ad = sbase +
                (uint32_t)(((b * 2) * SA_WORDS_PER + rowb * 12 + (lane >> 4) * 4) * 4);
            ldmx4(ah[tap], ad);
            ldmx4(al[tap], ad + SA_WORDS_PER * 4);
        }
        const unsigned int* sb = &smw[OFF_B + b * 4992];
#pragma unroll
        for (int nf = 0; nf < 13; ++nf)
#pragma unroll
            for (int tap = 0; tap < 3; ++tap) {
                uint2 bh = *reinterpret_cast<const uint2*>(
                    &sb[((nf * 3 + tap) * 2 + 0) * 64 + lane * 2]);
                uint2 bl = *reinterpret_cast<const uint2*>(
                    &sb[((nf * 3 + tap) * 2 + 1) * 64 + lane * 2]);
                mma_bf16(acc[nf], ah[tap], bh.x, bh.y);
                mma_bf16(acc[nf], al[tap], bh.x, bh.y);
                mma_bf16(acc[nf], ah[tap], bl.x, bl.y);
            }
        __syncthreads();
    }

    // epilogue: bias + relu; keep h-slots 1..6 and co < COUT
#pragma unroll
    for (int nf = 0; nf < 13; ++nf)
#pragma unroll
        for (int j = 0; j < 4; ++j) {
            int row = warp * 16 + (lane >> 2) + (j >> 1) * 8;
            int o = m0 + row, slot = o & 7;
            int n = nf * 8 + (lane & 3) * 2 + (j & 1);
            int co = co0 + n;
            if (slot >= 1 && slot <= 6 && co < COUT) {
                float v = fmaxf(acc[nf][j] + s_bias[n], 0.f);
                if (LAST) {
                    Oc[(size_t)(o >> 3) * 582 + co * 6 + (slot - 1)] = v;
                } else {
                    unsigned short hb = bf16_bits(v);
                    size_t p = (size_t)o * ONPAD + co;
                    Oh[p] = hb;
                    Ol[p] = bf16_bits(v - bf16_val(hb));
                }
            }
        }
}

// ---------------- K4: BN batch stats per channel ---------------------------
__global__ void bnstats_kernel(const float* __restrict__ gamma,
                               const float* __restrict__ beta) {
    __shared__ double s_s[256], s_q[256];
    int n = blockIdx.x;
    double s = 0.0, q = 0.0;
    for (int t = threadIdx.x; t < T_STEPS; t += 256) {
        const float* p = &g_c3[(size_t)t * 582 + n * 6];
#pragma unroll
        for (int hh = 0; hh < 6; ++hh) {
            double v = (double)p[hh];
            s += v; q += v * v;
        }
    }
    s_s[threadIdx.x] = s; s_q[threadIdx.x] = q;
    __syncthreads();
    for (int st = 128; st > 0; st >>= 1) {
        if (threadIdx.x < st) {
            s_s[threadIdx.x] += s_s[threadIdx.x + st];
            s_q[threadIdx.x] += s_q[threadIdx.x + st];
        }
        __syncthreads();
    }
    if (threadIdx.x == 0) {
        double N = (double)T_STEPS * 6.0;
        double mean = s_s[0] / N;
        double var = s_q[0] / N - mean * mean;
        float sc = gamma[n] * (float)(1.0 / sqrt(var + 1e-5));
        g_scale[n] = sc;
        g_shift[n] = beta[n] - (float)mean * sc;
    }
}

// ---------------- K5: fused BN apply + linear ------------------------------
__global__ void final_kernel(const float* __restrict__ Wl,
                             const float* __restrict__ bl,
                             float* __restrict__ out) {
    __shared__ float s_wl[36], s_bl[6];
    if (threadIdx.x < 36) s_wl[threadIdx.x] = Wl[threadIdx.x];
    if (threadIdx.x < 6)  s_bl[threadIdx.x] = bl[threadIdx.x];
    __syncthreads();

    int nt = blockIdx.x * blockDim.x + threadIdx.x;
    if (nt >= T_STEPS * NNODES) return;
    int n = nt % NNODES;
    float sc = __ldg(&g_scale[n]), sh = __ldg(&g_shift[n]);
    const float* p = &g_c3[(size_t)nt * 6];
    float v[6];
#pragma unroll
    for (int hh = 0; hh < 6; ++hh) v[hh] = fmaf(p[hh], sc, sh);
#pragma unroll
    for (int j = 0; j < 6; ++j) {
        float o = s_bl[j];
#pragma unroll
        for (int hh = 0; hh < 6; ++hh) o = fmaf(v[hh], s_wl[j * 6 + hh], o);
        out[nt * 6 + j] = o;
    }
}

// ---------------- launch ----------------------------------------------------
extern "C" void kernel_launch(void* const* d_in, const int* in_sizes, int n_in,
                              void* d_out, int out_size) {
    const float* X    = (const float*)d_in[1];
    const float* Wih  = (const float*)d_in[3];
    const float* Whh  = (const float*)d_in[4];
    const float* bih  = (const float*)d_in[5];
    const float* bhh  = (const float*)d_in[6];
    const float* Wc1  = (const float*)d_in[7];
    const float* bc1  = (const float*)d_in[8];
    const float* Wc2  = (const float*)d_in[9];
    const float* bc2  = (const float*)d_in[10];
    const float* Wc3  = (const float*)d_in[11];
    const float* bc3  = (const float*)d_in[12];
    const float* gamma = (const float*)d_in[13];
    const float* beta  = (const float*)d_in[14];
    const float* Wl   = (const float*)d_in[15];
    const float* bl   = (const float*)d_in[16];
    float* out = (float*)d_out;

    unsigned short *r1h, *r1l, *r2h, *r2l, *r3h, *r3l;
    unsigned int *b1, *b2, *b3;
    float* c3;
    cudaGetSymbolAddress((void**)&r1h, g_R1h);
    cudaGetSymbolAddress((void**)&r1l, g_R1l);
    cudaGetSymbolAddress((void**)&r2h, g_R2h);
    cudaGetSymbolAddress((void**)&r2l, g_R2l);
    cudaGetSymbolAddress((void**)&r3h, g_R3h);
    cudaGetSymbolAddress((void**)&r3l, g_R3l);
    cudaGetSymbolAddress((void**)&b1, g_B1);
    cudaGetSymbolAddress((void**)&b2, g_B2);
    cudaGetSymbolAddress((void**)&b3, g_B3);
    cudaGetSymbolAddress((void**)&c3, g_c3);

    cudaFuncSetAttribute(conv_mma<K1, 194, 26, K23, false>,
                         cudaFuncAttributeMaxDynamicSharedMemorySize, CONV_SMEM_B);
    cudaFuncSetAttribute(conv_mma<K23, 194, 26, K23, false>,
                         cudaFuncAttributeMaxDynamicSharedMemorySize, CONV_SMEM_B);
    cudaFuncSetAttribute(conv_mma<K23, 97, 13, K23, true>,
                         cudaFuncAttributeMaxDynamicSharedMemorySize, CONV_SMEM_B);

    const int NPACK = 7 * 26 * 384 + 13 * 26 * 384 + 13 * 13 * 384;
    pack_B<<<(NPACK + 255) / 256, 256>>>(Wc1, Wc2, Wc3);
    lstm_kernel<<<dim3(NCHUNK, 4), 160>>>(X, Wih, bih, bhh, Whh, r1h, r1l);
    conv_mma<K1, 194, 26, K23, false>
        <<<dim3(1024, 2), 256, CONV_SMEM_B>>>(r1h, r1l, b1, bc1, r2h, r2l, nullptr);
    conv_mma<K23, 194, 26, K23, false>
        <<<dim3(1024, 2), 256, CONV_SMEM_B>>>(r2h, r2l, b2, bc2, r3h, r3l, nullptr);
    conv_mma<K23, 97, 13, K23, true>
        <<<dim3(1024, 1), 256, CONV_SMEM_B>>>(r3h, r3l, b3, bc3, nullptr, nullptr, c3);
    bnstats_kernel<<<97, 256>>>(gamma, beta);
    final_kernel<<<(T_STEPS * NNODES + 255) / 256, 256>>>(Wl, bl, out);
}

// round 7
// speedup vs baseline: 2.5852x; 1.0957x over previous
#include <cuda_runtime.h>
#include <cuda_bf16.h>
#include <math.h>
#include <stdint.h>

#define T_STEPS 16384
#define NNODES  97
#define HID     6
#define ROWS_PAD (T_STEPS * 8)     // 131072 padded rows (8 h-slots per t)

#define NCHUNK  128
#define CHUNK   128
#define WARM    128

#define K1   112                    // conv1 K: 97 ci -> pad 112 (7 k16 chunks)
#define K23  208                    // conv2/3 K: 194 -> pad 208 (13 chunks)

// conv smem layout (words): 3 stages of [A(split0)1560 | A(split1)1560 | B 4992]
#define SA_WORDS      1560          // 130 rows * 12 words
#define STAGE_WORDS   8112          // 2*1560 + 4992
#define OFF_BIAS      24336         // 3 * 8112
#define CONV_SMEM_B   ((OFF_BIAS + 104) * 4)   // 97760 bytes

// ---------------- scratch (device globals; zero-initialized .bss) ----------
__device__ unsigned short g_R1h[(size_t)ROWS_PAD * K1];
__device__ unsigned short g_R1l[(size_t)ROWS_PAD * K1];
__device__ unsigned short g_R2h[(size_t)ROWS_PAD * K23];
__device__ unsigned short g_R2l[(size_t)ROWS_PAD * K23];
__device__ unsigned short g_R3h[(size_t)ROWS_PAD * K23];
__device__ unsigned short g_R3l[(size_t)ROWS_PAD * K23];
__device__ float g_c3[(size_t)T_STEPS * 582];
__device__ unsigned int g_B1[7  * 26 * 384];   // [kc][nf][tap][split][lane][reg]
__device__ unsigned int g_B2[13 * 26 * 384];
__device__ unsigned int g_B3[13 * 13 * 384];
__device__ float g_scale[NNODES];
__device__ float g_shift[NNODES];

// ---------------- helpers ---------------------------------------------------
__device__ __forceinline__ float sigf(float x) {
    return __fdividef(1.f, 1.f + __expf(-x));
}
__device__ __forceinline__ float tanh_f(float x) {
    float e = __expf(-2.f * fabsf(x));
    return copysignf(__fdividef(1.f - e, 1.f + e), x);
}
__device__ __forceinline__ uint32_t smem_u32(const void* p) {
    uint32_t a;
    asm("{ .reg .u64 t; cvta.to.shared.u64 t, %1; cvt.u32.u64 %0, t; }" : "=r"(a) : "l"(p));
    return a;
}
__device__ __forceinline__ uint64_t gptr(const void* p) {
    uint64_t g;
    asm("cvta.to.global.u64 %0, %1;" : "=l"(g) : "l"(p));
    return g;
}
__device__ __forceinline__ unsigned short bf16_bits(float v) {
    __nv_bfloat16 b = __float2bfloat16(v);
    return *reinterpret_cast<unsigned short*>(&b);
}
__device__ __forceinline__ float bf16_val(unsigned short u) {
    __nv_bfloat16 b = *reinterpret_cast<__nv_bfloat16*>(&u);
    return __bfloat162float(b);
}
__device__ __forceinline__ void ldmx4(uint32_t* r, uint32_t addr) {
    asm volatile("ldmatrix.sync.aligned.m8n8.x4.shared.b16 {%0,%1,%2,%3}, [%4];"
                 : "=r"(r[0]), "=r"(r[1]), "=r"(r[2]), "=r"(r[3]) : "r"(addr));
}
__device__ __forceinline__ void mma_bf16(float* d, const uint32_t* a, uint32_t b0, uint32_t b1) {
    asm volatile(
        "mma.sync.aligned.m16n8k16.row.col.f32.bf16.bf16.f32 "
        "{%0,%1,%2,%3}, {%4,%5,%6,%7}, {%8,%9}, {%0,%1,%2,%3};"
        : "+f"(d[0]), "+f"(d[1]), "+f"(d[2]), "+f"(d[3])
        : "r"(a[0]), "r"(a[1]), "r"(a[2]), "r"(a[3]), "r"(b0), "r"(b1));
}
template <int N>
__device__ __forceinline__ void cp_wait() {
    asm volatile("cp.async.wait_group %0;" :: "n"(N) : "memory");
}

// ---------------- K0: pack tap weights into mma B-fragment layout -----------
__global__ void pack_B(const float* __restrict__ Wc1,
                       const float* __restrict__ Wc2,
                       const float* __restrict__ Wc3) {
    const int N1 = 7 * 26 * 384, N2 = 13 * 26 * 384, N3 = 13 * 13 * 384;
    int idx = blockIdx.x * 256 + threadIdx.x;
    const float* W; unsigned int* dst; int NFALL, CIN, COUT, li;
    if (idx < N1)           { W = Wc1; dst = g_B1; NFALL = 26; CIN = 97;  COUT = 194; li = idx; }
    else if (idx < N1 + N2) { W = Wc2; dst = g_B2; NFALL = 26; CIN = 194; COUT = 194; li = idx - N1; }
    else if (idx < N1 + N2 + N3) { W = Wc3; dst = g_B3; NFALL = 13; CIN = 194; COUT = 97; li = idx - N1 - N2; }
    else return;

    int reg   = li & 1;
    int lane  = (li >> 1) & 31;
    int split = (li >> 6) & 1;
    int tap   = (li / 128) % 3;
    int nf    = (li / 384) % NFALL;
    int kc    = li / (384 * NFALL);

    int n  = nf * 8 + (lane >> 2);
    int k0 = kc * 16 + (lane & 3) * 2 + reg * 8;
    float w0 = 0.f, w1 = 0.f;
    if (n < COUT) {
        if (k0 < CIN)     w0 = W[((n * CIN + k0) * 3 + tap) * 3 + 1];
        if (k0 + 1 < CIN) w1 = W[((n * CIN + k0 + 1) * 3 + tap) * 3 + 1];
    }
    unsigned short h0, h1;
    if (split == 0) { h0 = bf16_bits(w0); h1 = bf16_bits(w1); }
    else {
        h0 = bf16_bits(w0 - bf16_val(bf16_bits(w0)));
        h1 = bf16_bits(w1 - bf16_val(bf16_bits(w1)));
    }
    dst[li] = (unsigned int)h0 | ((unsigned int)h1 << 16);
}

// ---------------- K1: fused x-projection + chunked LSTM ---------------------
// Blocked (8-step) double-buffered X prefetch: loads for block b+1 are issued
// before computing block b, hiding the ~700cyc gmem latency behind 8 steps.
__global__ void lstm_kernel(const float* __restrict__ X,
                            const float* __restrict__ Wih,
                            const float* __restrict__ bih,
                            const float* __restrict__ bhh,
                            const float* __restrict__ Whh,
                            unsigned short* __restrict__ R1h,
                            unsigned short* __restrict__ R1l) {
    int lane = threadIdx.x & 31;
    int w    = threadIdx.x >> 5;
    int g    = lane / 6;
    int j    = lane % 6;
    int node = blockIdx.y * 25 + w * 5 + g;
    bool active = (lane < 30) && (node < NNODES);
    int nn = active ? node : 0;

    float Wx[4][12], Wr[4][6], bsum[4];
#pragma unroll
    for (int gi = 0; gi < 4; ++gi) {
        int row = gi * 6 + j;
        bsum[gi] = __ldg(&bih[row]) + __ldg(&bhh[row]);
#pragma unroll
        for (int f = 0; f < 12; ++f) Wx[gi][f] = __ldg(&Wih[row * 12 + f]);
#pragma unroll
        for (int k = 0; k < 6; ++k)  Wr[gi][k] = __ldg(&Whh[row * 6 + k]);
    }

    float h = 0.f, c = 0.f;
    int t0 = blockIdx.x * CHUNK;
    int tb = t0 - WARM; if (tb < 0) tb = 0;
    int te = t0 + CHUNK;
    int base = g * 6;

    float2 xs[2][8];
#pragma unroll
    for (int u = 0; u < 8; ++u)
        xs[0][u] = __ldg(reinterpret_cast<const float2*>(
            X + ((size_t)(tb + u) * NNODES + nn) * 12 + 2 * j));

    int pb = 0;
    for (int tB = tb; tB < te; tB += 8, pb ^= 1) {
        if (tB + 8 < te) {
#pragma unroll
            for (int u = 0; u < 8; ++u)
                xs[pb ^ 1][u] = __ldg(reinterpret_cast<const float2*>(
                    X + ((size_t)(tB + 8 + u) * NNODES + nn) * 12 + 2 * j));
        }
#pragma unroll
        for (int u = 0; u < 8; ++u) {
            int t = tB + u;
            float2 xp = xs[pb][u];
            float xv[12];
#pragma unroll
            for (int m = 0; m < 6; ++m) {
                xv[2 * m]     = __shfl_sync(0xffffffffu, xp.x, base + m);
                xv[2 * m + 1] = __shfl_sync(0xffffffffu, xp.y, base + m);
            }
            float gate[4];
#pragma unroll
            for (int gi = 0; gi < 4; ++gi) {
                float s = bsum[gi];
#pragma unroll
                for (int f = 0; f < 12; ++f) s = fmaf(Wx[gi][f], xv[f], s);
                gate[gi] = s;
            }
            float hs[6];
#pragma unroll
            for (int k = 0; k < 6; ++k) hs[k] = __shfl_sync(0xffffffffu, h, base + k);
#pragma unroll
            for (int k = 0; k < 6; ++k) {
                gate[0] = fmaf(Wr[0][k], hs[k], gate[0]);
                gate[1] = fmaf(Wr[1][k], hs[k], gate[1]);
                gate[2] = fmaf(Wr[2][k], hs[k], gate[2]);
                gate[3] = fmaf(Wr[3][k], hs[k], gate[3]);
            }
            float ai = sigf(gate[0]), af = sigf(gate[1]);
            float ag = tanh_f(gate[2]), ao = sigf(gate[3]);
            c = fmaf(af, c, ai * ag);
            h = tanh_f(ao * tanh_f(c));
            if (t >= t0 && active) {
                size_t p = ((size_t)t * 8 + j + 1) * K1 + node;
                unsigned short hb = bf16_bits(h);
                R1h[p] = hb;
                R1l[p] = bf16_bits(h - bf16_val(hb));
            }
        }
    }
}

// ---------------- conv tile prefetch via cp.async ---------------------------
template <int KPAD, int NFALL>
__device__ __forceinline__ void conv_prefetch(
    const unsigned short* Rh, const unsigned short* Rl,
    const unsigned int* Bpk, int m0, int ycol, int kc, int stage,
    int tid, uint32_t sbase) {
    const uint32_t soff = sbase + (uint32_t)(stage * STAGE_WORDS * 4);
    // A tile: 130 rows x (2 splits x 2 halves of 16B)
#pragma unroll 1
    for (int i = tid; i < 520; i += 256) {
        int row = i >> 2, sub = i & 3;
        int split = sub >> 1, half = sub & 1;
        int r = m0 - 1 + row;
        int ok = (r >= 0 && r < ROWS_PAD);
        int rc = ok ? r : 0;
        const unsigned short* src = (split ? Rl : Rh) +
            (size_t)rc * KPAD + kc * 16 + half * 8;
        uint32_t dst = soff +
            (uint32_t)((split * SA_WORDS + row * 12 + half * 4) * 4);
        unsigned sz = ok ? 16u : 0u;
        asm volatile("cp.async.cg.shared.global [%0], [%1], 16, %2;"
                     :: "r"(dst), "l"(gptr(src)), "r"(sz) : "memory");
    }
    // B slice: 13 nf x 384 words
    const unsigned int* bsrc = Bpk + ((size_t)kc * NFALL + ycol * 13) * 384;
#pragma unroll 1
    for (int i = tid; i < 1248; i += 256) {
        uint32_t dst = soff + (uint32_t)((2 * SA_WORDS + i * 4) * 4);
        asm volatile("cp.async.cg.shared.global [%0], [%1], 16, %2;"
                     :: "r"(dst), "l"(gptr(bsrc + i * 4)), "r"(16u) : "memory");
    }
    asm volatile("cp.async.commit_group;" ::: "memory");
}

// ---------------- K3: tap-decomposed conv GEMM, 3-stage single-sync ---------
// CTA tile: M=128 rows x N=104 cols; 8 warps x m16; 3-stage cp.async ring with
// ONE __syncthreads per stage (barrier at stage start proves stage kc-1 fully
// consumed, so prefetch(kc+2) may overwrite its buffer).
template <int KPAD, int COUT, int NFALL, int ONPAD, bool LAST>
__global__ void __launch_bounds__(256, 2)
conv_mma(const unsigned short* __restrict__ Rh, const unsigned short* __restrict__ Rl,
         const unsigned int* __restrict__ Bpk, const float* __restrict__ bias,
         unsigned short* __restrict__ Oh, unsigned short* __restrict__ Ol,
         float* __restrict__ Oc) {
    extern __shared__ unsigned int smw[];
    const uint32_t sbase = smem_u32(smw);
    float* s_bias = reinterpret_cast<float*>(smw + OFF_BIAS);

    const int tid = threadIdx.x, warp = tid >> 5, lane = tid & 31;
    const int m0  = blockIdx.x * 128;
    const int co0 = blockIdx.y * 104;
    if (tid < 104) s_bias[tid] = (co0 + tid < COUT) ? __ldg(&bias[co0 + tid]) : 0.f;

    float acc[13][4];
#pragma unroll
    for (int nf = 0; nf < 13; ++nf)
#pragma unroll
        for (int j = 0; j < 4; ++j) acc[nf][j] = 0.f;

    const int NK = KPAD / 16;
    conv_prefetch<KPAD, NFALL>(Rh, Rl, Bpk, m0, blockIdx.y, 0, 0, tid, sbase);
    conv_prefetch<KPAD, NFALL>(Rh, Rl, Bpk, m0, blockIdx.y, 1, 1, tid, sbase);

    for (int kc = 0; kc < NK; ++kc) {
        if (kc + 1 < NK) cp_wait<1>(); else cp_wait<0>();
        __syncthreads();
        if (kc + 2 < NK)
            conv_prefetch<KPAD, NFALL>(Rh, Rl, Bpk, m0, blockIdx.y,
                                       kc + 2, (kc + 2) % 3, tid, sbase);
        const int st = kc % 3;
        const uint32_t aoff = sbase + (uint32_t)(st * STAGE_WORDS * 4);

        uint32_t ah[3][4], al[3][4];
#pragma unroll
        for (int tap = 0; tap < 3; ++tap) {
            int rowb = warp * 16 + tap + (lane & 15);
            uint32_t ad = aoff + (uint32_t)((rowb * 12 + (lane >> 4) * 4) * 4);
            ldmx4(ah[tap], ad);
            ldmx4(al[tap], ad + SA_WORDS * 4);
        }
        const unsigned int* sb = &smw[st * STAGE_WORDS + 2 * SA_WORDS];
#pragma unroll
        for (int nf = 0; nf < 13; ++nf)
#pragma unroll
            for (int tap = 0; tap < 3; ++tap) {
                uint2 bh = *reinterpret_cast<const uint2*>(
                    &sb[((nf * 3 + tap) * 2 + 0) * 64 + lane * 2]);
                uint2 bl = *reinterpret_cast<const uint2*>(
                    &sb[((nf * 3 + tap) * 2 + 1) * 64 + lane * 2]);
                mma_bf16(acc[nf], ah[tap], bh.x, bh.y);
                mma_bf16(acc[nf], al[tap], bh.x, bh.y);
                mma_bf16(acc[nf], ah[tap], bl.x, bl.y);
            }
    }

    // epilogue: bias + relu; keep h-slots 1..6 and co < COUT
#pragma unroll
    for (int nf = 0; nf < 13; ++nf)
#pragma unroll
        for (int j = 0; j < 4; ++j) {
            int row = warp * 16 + (lane >> 2) + (j >> 1) * 8;
            int o = m0 + row, slot = o & 7;
            int n = nf * 8 + (lane & 3) * 2 + (j & 1);
            int co = co0 + n;
            if (slot >= 1 && slot <= 6 && co < COUT) {
                float v = fmaxf(acc[nf][j] + s_bias[n], 0.f);
                if (LAST) {
                    Oc[(size_t)(o >> 3) * 582 + co * 6 + (slot - 1)] = v;
                } else {
                    unsigned short hb = bf16_bits(v);
                    size_t p = (size_t)o * ONPAD + co;
                    Oh[p] = hb;
                    Ol[p] = bf16_bits(v - bf16_val(hb));
                }
            }
        }
}

// ---------------- K4: BN batch stats per channel ---------------------------
__global__ void bnstats_kernel(const float* __restrict__ gamma,
                               const float* __restrict__ beta) {
    __shared__ double s_s[256], s_q[256];
    int n = blockIdx.x;
    double s = 0.0, q = 0.0;
    for (int t = threadIdx.x; t < T_STEPS; t += 256) {
        const float* p = &g_c3[(size_t)t * 582 + n * 6];
#pragma unroll
        for (int hh = 0; hh < 6; ++hh) {
            double v = (double)p[hh];
            s += v; q += v * v;
        }
    }
    s_s[threadIdx.x] = s; s_q[threadIdx.x] = q;
    __syncthreads();
    for (int st = 128; st > 0; st >>= 1) {
        if (threadIdx.x < st) {
            s_s[threadIdx.x] += s_s[threadIdx.x + st];
            s_q[threadIdx.x] += s_q[threadIdx.x + st];
        }
        __syncthreads();
    }
    if (threadIdx.x == 0) {
        double N = (double)T_STEPS * 6.0;
        double mean = s_s[0] / N;
        double var = s_q[0] / N - mean * mean;
        float sc = gamma[n] * (float)(1.0 / sqrt(var + 1e-5));
        g_scale[n] = sc;
        g_shift[n] = beta[n] - (float)mean * sc;
    }
}

// ---------------- K5: fused BN apply + linear ------------------------------
__global__ void final_kernel(const float* __restrict__ Wl,
                             const float* __restrict__ bl,
                             float* __restrict__ out) {
    __shared__ float s_wl[36], s_bl[6];
    if (threadIdx.x < 36) s_wl[threadIdx.x] = Wl[threadIdx.x];
    if (threadIdx.x < 6)  s_bl[threadIdx.x] = bl[threadIdx.x];
    __syncthreads();

    int nt = blockIdx.x * blockDim.x + threadIdx.x;
    if (nt >= T_STEPS * NNODES) return;
    int n = nt % NNODES;
    float sc = __ldg(&g_scale[n]), sh = __ldg(&g_shift[n]);
    const float* p = &g_c3[(size_t)nt * 6];
    float v[6];
#pragma unroll
    for (int hh = 0; hh < 6; ++hh) v[hh] = fmaf(p[hh], sc, sh);
#pragma unroll
    for (int j = 0; j < 6; ++j) {
        float o = s_bl[j];
#pragma unroll
        for (int hh = 0; hh < 6; ++hh) o = fmaf(v[hh], s_wl[j * 6 + hh], o);
        out[nt * 6 + j] = o;
    }
}

// ---------------- launch ----------------------------------------------------
extern "C" void kernel_launch(void* const* d_in, const int* in_sizes, int n_in,
                              void* d_out, int out_size) {
    const float* X    = (const float*)d_in[1];
    const float* Wih  = (const float*)d_in[3];
    const float* Whh  = (const float*)d_in[4];
    const float* bih  = (const float*)d_in[5];
    const float* bhh  = (const float*)d_in[6];
    const float* Wc1  = (const float*)d_in[7];
    const float* bc1  = (const float*)d_in[8];
    const float* Wc2  = (const float*)d_in[9];
    const float* bc2  = (const float*)d_in[10];
    const float* Wc3  = (const float*)d_in[11];
    const float* bc3  = (const float*)d_in[12];
    const float* gamma = (const float*)d_in[13];
    const float* beta  = (const float*)d_in[14];
    const float* Wl   = (const float*)d_in[15];
    const float* bl   = (const float*)d_in[16];
    float* out = (float*)d_out;

    unsigned short *r1h, *r1l, *r2h, *r2l, *r3h, *r3l;
    unsigned int *b1, *b2, *b3;
    float* c3;
    cudaGetSymbolAddress((void**)&r1h, g_R1h);
    cudaGetSymbolAddress((void**)&r1l, g_R1l);
    cudaGetSymbolAddress((void**)&r2h, g_R2h);
    cudaGetSymbolAddress((void**)&r2l, g_R2l);
    cudaGetSymbolAddress((void**)&r3h, g_R3h);
    cudaGetSymbolAddress((void**)&r3l, g_R3l);
    cudaGetSymbolAddress((void**)&b1, g_B1);
    cudaGetSymbolAddress((void**)&b2, g_B2);
    cudaGetSymbolAddress((void**)&b3, g_B3);
    cudaGetSymbolAddress((void**)&c3, g_c3);

    cudaFuncSetAttribute(conv_mma<K1, 194, 26, K23, false>,
                         cudaFuncAttributeMaxDynamicSharedMemorySize, CONV_SMEM_B);
    cudaFuncSetAttribute(conv_mma<K23, 194, 26, K23, false>,
                         cudaFuncAttributeMaxDynamicSharedMemorySize, CONV_SMEM_B);
    cudaFuncSetAttribute(conv_mma<K23, 97, 13, K23, true>,
                         cudaFuncAttributeMaxDynamicSharedMemorySize, CONV_SMEM_B);

    const int NPACK = 7 * 26 * 384 + 13 * 26 * 384 + 13 * 13 * 384;
    pack_B<<<(NPACK + 255) / 256, 256>>>(Wc1, Wc2, Wc3);
    lstm_kernel<<<dim3(NCHUNK, 4), 160>>>(X, Wih, bih, bhh, Whh, r1h, r1l);
    conv_mma<K1, 194, 26, K23, false>
        <<<dim3(1024, 2), 256, CONV_SMEM_B>>>(r1h, r1l, b1, bc1, r2h, r2l, nullptr);
    conv_mma<K23, 194, 26, K23, false>
        <<<dim3(1024, 2), 256, CONV_SMEM_B>>>(r2h, r2l, b2, bc2, r3h, r3l, nullptr);
    conv_mma<K23, 97, 13, K23, true>
        <<<dim3(1024, 1), 256, CONV_SMEM_B>>>(r3h, r3l, b3, bc3, nullptr, nullptr, c3);
    bnstats_kernel<<<97, 256>>>(gamma, beta);
    final_kernel<<<(T_STEPS * NNODES + 255) / 256, 256>>>(Wl, bl, out);
}

// round 8
// speedup vs baseline: 3.3862x; 1.3098x over previous
#include <cuda_runtime.h>
#include <cuda_fp16.h>
#include <math.h>
#include <stdint.h>

#define T_STEPS 16384
#define NNODES  97
#define HID     6
#define ROWS_PAD (T_STEPS * 8)     // 131072 padded rows (8 h-slots per t)

#define NCHUNK  128
#define CHUNK   128
#define WARM    128

#define K1   112                    // conv1 K: 97 ci -> pad 112 (7 k16 chunks)
#define K23  208                    // conv2/3 K: 194 -> pad 208 (13 chunks)

// conv smem layout (words): 3 stages of [A(hi)1560 | A(lo)1560 | B 2496]
#define SA_WORDS      1560          // 130 rows * 12 words
#define SB_WORDS      2496          // 13 nf * 3 tap * 64
#define STAGE_WORDS   5616          // 2*1560 + 2496
#define OFF_BIAS      16848         // 3 * 5616
#define CONV_SMEM_B   ((OFF_BIAS + 104) * 4)   // 67808 bytes

// ---------------- scratch (device globals; zero-initialized .bss) ----------
__device__ unsigned short g_R1h[(size_t)ROWS_PAD * K1];
__device__ unsigned short g_R1l[(size_t)ROWS_PAD * K1];
__device__ unsigned short g_R2h[(size_t)ROWS_PAD * K23];
__device__ unsigned short g_R2l[(size_t)ROWS_PAD * K23];
__device__ unsigned short g_R3h[(size_t)ROWS_PAD * K23];
__device__ unsigned short g_R3l[(size_t)ROWS_PAD * K23];
__device__ float g_c3[(size_t)T_STEPS * 582];
__device__ unsigned int g_B1[7  * 26 * 192];   // [kc][nf][tap][lane][reg], fp16x2
__device__ unsigned int g_B2[13 * 26 * 192];
__device__ unsigned int g_B3[13 * 13 * 192];
__device__ float g_scale[NNODES];
__device__ float g_shift[NNODES];

// ---------------- helpers ---------------------------------------------------
__device__ __forceinline__ float sigf(float x) {
    return __fdividef(1.f, 1.f + __expf(-x));
}
__device__ __forceinline__ float tanh_f(float x) {
    float e = __expf(-2.f * fabsf(x));
    return copysignf(__fdividef(1.f - e, 1.f + e), x);
}
__device__ __forceinline__ uint32_t smem_u32(const void* p) {
    uint32_t a;
    asm("{ .reg .u64 t; cvta.to.shared.u64 t, %1; cvt.u32.u64 %0, t; }" : "=r"(a) : "l"(p));
    return a;
}
__device__ __forceinline__ uint64_t gptr(const void* p) {
    uint64_t g;
    asm("cvta.to.global.u64 %0, %1;" : "=l"(g) : "l"(p));
    return g;
}
__device__ __forceinline__ unsigned short f16_bits(float v) {
    __half h = __float2half_rn(v);
    return *reinterpret_cast<unsigned short*>(&h);
}
__device__ __forceinline__ float f16_val(unsigned short u) {
    __half h = *reinterpret_cast<__half*>(&u);
    return __half2float(h);
}
__device__ __forceinline__ void ldmx4(uint32_t* r, uint32_t addr) {
    asm volatile("ldmatrix.sync.aligned.m8n8.x4.shared.b16 {%0,%1,%2,%3}, [%4];"
                 : "=r"(r[0]), "=r"(r[1]), "=r"(r[2]), "=r"(r[3]) : "r"(addr));
}
__device__ __forceinline__ void mma_f16(float* d, const uint32_t* a, uint32_t b0, uint32_t b1) {
    asm volatile(
        "mma.sync.aligned.m16n8k16.row.col.f32.f16.f16.f32 "
        "{%0,%1,%2,%3}, {%4,%5,%6,%7}, {%8,%9}, {%0,%1,%2,%3};"
        : "+f"(d[0]), "+f"(d[1]), "+f"(d[2]), "+f"(d[3])
        : "r"(a[0]), "r"(a[1]), "r"(a[2]), "r"(a[3]), "r"(b0), "r"(b1));
}
template <int N>
__device__ __forceinline__ void cp_wait() {
    asm volatile("cp.async.wait_group %0;" :: "n"(N) : "memory");
}

// ---------------- K0: pack tap weights into mma B-fragment layout (fp16) ----
__global__ void pack_B(const float* __restrict__ Wc1,
                       const float* __restrict__ Wc2,
                       const float* __restrict__ Wc3) {
    const int N1 = 7 * 26 * 192, N2 = 13 * 26 * 192, N3 = 13 * 13 * 192;
    int idx = blockIdx.x * 256 + threadIdx.x;
    const float* W; unsigned int* dst; int NFALL, CIN, COUT, li;
    if (idx < N1)           { W = Wc1; dst = g_B1; NFALL = 26; CIN = 97;  COUT = 194; li = idx; }
    else if (idx < N1 + N2) { W = Wc2; dst = g_B2; NFALL = 26; CIN = 194; COUT = 194; li = idx - N1; }
    else if (idx < N1 + N2 + N3) { W = Wc3; dst = g_B3; NFALL = 13; CIN = 194; COUT = 97; li = idx - N1 - N2; }
    else return;

    int reg   = li & 1;
    int lane  = (li >> 1) & 31;
    int tap   = (li >> 6) % 3;
    int nf    = (li / 192) % NFALL;
    int kc    = li / (192 * NFALL);

    int n  = nf * 8 + (lane >> 2);
    int k0 = kc * 16 + (lane & 3) * 2 + reg * 8;
    float w0 = 0.f, w1 = 0.f;
    if (n < COUT) {
        if (k0 < CIN)     w0 = W[((n * CIN + k0) * 3 + tap) * 3 + 1];
        if (k0 + 1 < CIN) w1 = W[((n * CIN + k0 + 1) * 3 + tap) * 3 + 1];
    }
    dst[li] = (unsigned int)f16_bits(w0) | ((unsigned int)f16_bits(w1) << 16);
}

// ---------------- K1: fused x-projection + chunked LSTM ---------------------
__global__ void lstm_kernel(const float* __restrict__ X,
                            const float* __restrict__ Wih,
                            const float* __restrict__ bih,
                            const float* __restrict__ bhh,
                            const float* __restrict__ Whh,
                            unsigned short* __restrict__ R1h,
                            unsigned short* __restrict__ R1l) {
    int lane = threadIdx.x & 31;
    int w    = threadIdx.x >> 5;
    int g    = lane / 6;
    int j    = lane % 6;
    int node = blockIdx.y * 25 + w * 5 + g;
    bool active = (lane < 30) && (node < NNODES);
    int nn = active ? node : 0;

    float Wx[4][12], Wr[4][6], bsum[4];
#pragma unroll
    for (int gi = 0; gi < 4; ++gi) {
        int row = gi * 6 + j;
        bsum[gi] = __ldg(&bih[row]) + __ldg(&bhh[row]);
#pragma unroll
        for (int f = 0; f < 12; ++f) Wx[gi][f] = __ldg(&Wih[row * 12 + f]);
#pragma unroll
        for (int k = 0; k < 6; ++k)  Wr[gi][k] = __ldg(&Whh[row * 6 + k]);
    }

    float h = 0.f, c = 0.f;
    int t0 = blockIdx.x * CHUNK;
    int tb = t0 - WARM; if (tb < 0) tb = 0;
    int te = t0 + CHUNK;
    int base = g * 6;

    float2 xs[2][8];
#pragma unroll
    for (int u = 0; u < 8; ++u)
        xs[0][u] = __ldg(reinterpret_cast<const float2*>(
            X + ((size_t)(tb + u) * NNODES + nn) * 12 + 2 * j));

    int pb = 0;
    for (int tB = tb; tB < te; tB += 8, pb ^= 1) {
        if (tB + 8 < te) {
#pragma unroll
            for (int u = 0; u < 8; ++u)
                xs[pb ^ 1][u] = __ldg(reinterpret_cast<const float2*>(
                    X + ((size_t)(tB + 8 + u) * NNODES + nn) * 12 + 2 * j));
        }
#pragma unroll
        for (int u = 0; u < 8; ++u) {
            int t = tB + u;
            float2 xp = xs[pb][u];
            float xv[12];
#pragma unroll
            for (int m = 0; m < 6; ++m) {
                xv[2 * m]     = __shfl_sync(0xffffffffu, xp.x, base + m);
                xv[2 * m + 1] = __shfl_sync(0xffffffffu, xp.y, base + m);
            }
            float gate[4];
#pragma unroll
            for (int gi = 0; gi < 4; ++gi) {
                float s = bsum[gi];
#pragma unroll
                for (int f = 0; f < 12; ++f) s = fmaf(Wx[gi][f], xv[f], s);
                gate[gi] = s;
            }
            float hs[6];
#pragma unroll
            for (int k = 0; k < 6; ++k) hs[k] = __shfl_sync(0xffffffffu, h, base + k);
#pragma unroll
            for (int k = 0; k < 6; ++k) {
                gate[0] = fmaf(Wr[0][k], hs[k], gate[0]);
                gate[1] = fmaf(Wr[1][k], hs[k], gate[1]);
                gate[2] = fmaf(Wr[2][k], hs[k], gate[2]);
                gate[3] = fmaf(Wr[3][k], hs[k], gate[3]);
            }
            float ai = sigf(gate[0]), af = sigf(gate[1]);
            float ag = tanh_f(gate[2]), ao = sigf(gate[3]);
            c = fmaf(af, c, ai * ag);
            h = tanh_f(ao * tanh_f(c));
            if (t >= t0 && active) {
                size_t p = ((size_t)t * 8 + j + 1) * K1 + node;
                unsigned short hb = f16_bits(h);
                R1h[p] = hb;
                R1l[p] = f16_bits(h - f16_val(hb));
            }
        }
    }
}

// ---------------- conv tile prefetch via cp.async ---------------------------
template <int KPAD, int NFALL>
__device__ __forceinline__ void conv_prefetch(
    const unsigned short* Rh, const unsigned short* Rl,
    const unsigned int* Bpk, int m0, int ycol, int kc, int stage,
    int tid, uint32_t sbase) {
    const uint32_t soff = sbase + (uint32_t)(stage * STAGE_WORDS * 4);
    // A tile: 130 rows x (2 splits x 2 halves of 16B)
#pragma unroll 1
    for (int i = tid; i < 520; i += 256) {
        int row = i >> 2, sub = i & 3;
        int split = sub >> 1, half = sub & 1;
        int r = m0 - 1 + row;
        int ok = (r >= 0 && r < ROWS_PAD);
        int rc = ok ? r : 0;
        const unsigned short* src = (split ? Rl : Rh) +
            (size_t)rc * KPAD + kc * 16 + half * 8;
        uint32_t dst = soff +
            (uint32_t)((split * SA_WORDS + row * 12 + half * 4) * 4);
        unsigned sz = ok ? 16u : 0u;
        asm volatile("cp.async.cg.shared.global [%0], [%1], 16, %2;"
                     :: "r"(dst), "l"(gptr(src)), "r"(sz) : "memory");
    }
    // B slice: 13 nf x 192 words
    const unsigned int* bsrc = Bpk + ((size_t)kc * NFALL + ycol * 13) * 192;
#pragma unroll 1
    for (int i = tid; i < 624; i += 256) {
        uint32_t dst = soff + (uint32_t)((2 * SA_WORDS + i * 4) * 4);
        asm volatile("cp.async.cg.shared.global [%0], [%1], 16, %2;"
                     :: "r"(dst), "l"(gptr(bsrc + i * 4)), "r"(16u) : "memory");
    }
    asm volatile("cp.async.commit_group;" ::: "memory");
}

// ---------------- K3: tap-decomposed conv GEMM, fp16 2-term split -----------
// CTA tile: M=128 rows x N=104 cols; 8 warps x m16; 3-stage cp.async ring,
// one __syncthreads per stage. A exact fp16 hi+lo; B single fp16 (err ~2^-12).
template <int KPAD, int COUT, int NFALL, int ONPAD, bool LAST>
__global__ void __launch_bounds__(256, 2)
conv_mma(const unsigned short* __restrict__ Rh, const unsigned short* __restrict__ Rl,
         const unsigned int* __restrict__ Bpk, const float* __restrict__ bias,
         unsigned short* __restrict__ Oh, unsigned short* __restrict__ Ol,
         float* __restrict__ Oc) {
    extern __shared__ unsigned int smw[];
    const uint32_t sbase = smem_u32(smw);
    float* s_bias = reinterpret_cast<float*>(smw + OFF_BIAS);

    const int tid = threadIdx.x, warp = tid >> 5, lane = tid & 31;
    const int m0  = blockIdx.x * 128;
    const int co0 = blockIdx.y * 104;
    if (tid < 104) s_bias[tid] = (co0 + tid < COUT) ? __ldg(&bias[co0 + tid]) : 0.f;

    float acc[13][4];
#pragma unroll
    for (int nf = 0; nf < 13; ++nf)
#pragma unroll
        for (int j = 0; j < 4; ++j) acc[nf][j] = 0.f;

    const int NK = KPAD / 16;
    conv_prefetch<KPAD, NFALL>(Rh, Rl, Bpk, m0, blockIdx.y, 0, 0, tid, sbase);
    conv_prefetch<KPAD, NFALL>(Rh, Rl, Bpk, m0, blockIdx.y, 1, 1, tid, sbase);

    for (int kc = 0; kc < NK; ++kc) {
        if (kc + 1 < NK) cp_wait<1>(); else cp_wait<0>();
        __syncthreads();
        if (kc + 2 < NK)
            conv_prefetch<KPAD, NFALL>(Rh, Rl, Bpk, m0, blockIdx.y,
                                       kc + 2, (kc + 2) % 3, tid, sbase);
        const int st = kc % 3;
        const uint32_t aoff = sbase + (uint32_t)(st * STAGE_WORDS * 4);

        uint32_t ah[3][4], al[3][4];
#pragma unroll
        for (int tap = 0; tap < 3; ++tap) {
            int rowb = warp * 16 + tap + (lane & 15);
            uint32_t ad = aoff + (uint32_t)((rowb * 12 + (lane >> 4) * 4) * 4);
            ldmx4(ah[tap], ad);
            ldmx4(al[tap], ad + SA_WORDS * 4);
        }
        const unsigned int* sb = &smw[st * STAGE_WORDS + 2 * SA_WORDS];
#pragma unroll
        for (int nf = 0; nf < 13; ++nf)
#pragma unroll
            for (int tap = 0; tap < 3; ++tap) {
                uint2 bb = *reinterpret_cast<const uint2*>(
                    &sb[(nf * 3 + tap) * 64 + lane * 2]);
                mma_f16(acc[nf], ah[tap], bb.x, bb.y);
                mma_f16(acc[nf], al[tap], bb.x, bb.y);
            }
    }

    // epilogue: bias + relu; keep h-slots 1..6 and co < COUT
#pragma unroll
    for (int nf = 0; nf < 13; ++nf)
#pragma unroll
        for (int j = 0; j < 4; ++j) {
            int row = warp * 16 + (lane >> 2) + (j >> 1) * 8;
            int o = m0 + row, slot = o & 7;
            int n = nf * 8 + (lane & 3) * 2 + (j & 1);
            int co = co0 + n;
            if (slot >= 1 && slot <= 6 && co < COUT) {
                float v = fmaxf(acc[nf][j] + s_bias[n], 0.f);
                if (LAST) {
                    Oc[(size_t)(o >> 3) * 582 + co * 6 + (slot - 1)] = v;
                } else {
                    unsigned short hb = f16_bits(v);
                    size_t p = (size_t)o * ONPAD + co;
                    Oh[p] = hb;
                    Ol[p] = f16_bits(v - f16_val(hb));
                }
            }
        }
}

// ---------------- K4: BN batch stats per channel ---------------------------
__global__ void bnstats_kernel(const float* __restrict__ gamma,
                               const float* __restrict__ beta) {
    __shared__ double s_s[256], s_q[256];
    int n = blockIdx.x;
    double s = 0.0, q = 0.0;
    for (int t = threadIdx.x; t < T_STEPS; t += 256) {
        const float* p = &g_c3[(size_t)t * 582 + n * 6];
#pragma unroll
        for (int hh = 0; hh < 6; ++hh) {
            double v = (double)p[hh];
            s += v; q += v * v;
        }
    }
    s_s[threadIdx.x] = s; s_q[threadIdx.x] = q;
    __syncthreads();
    for (int st = 128; st > 0; st >>= 1) {
        if (threadIdx.x < st) {
            s_s[threadIdx.x] += s_s[threadIdx.x + st];
            s_q[threadIdx.x] += s_q[threadIdx.x + st];
        }
        __syncthreads();
    }
    if (threadIdx.x == 0) {
        double N = (double)T_STEPS * 6.0;
        double mean = s_s[0] / N;
        double var = s_q[0] / N - mean * mean;
        float sc = gamma[n] * (float)(1.0 / sqrt(var + 1e-5));
        g_scale[n] = sc;
        g_shift[n] = beta[n] - (float)mean * sc;
    }
}

// ---------------- K5: fused BN apply + linear ------------------------------
__global__ void final_kernel(const float* __restrict__ Wl,
                             const float* __restrict__ bl,
                             float* __restrict__ out) {
    __shared__ float s_wl[36], s_bl[6];
    if (threadIdx.x < 36) s_wl[threadIdx.x] = Wl[threadIdx.x];
    if (threadIdx.x < 6)  s_bl[threadIdx.x] = bl[threadIdx.x];
    __syncthreads();

    int nt = blockIdx.x * blockDim.x + threadIdx.x;
    if (nt >= T_STEPS * NNODES) return;
    int n = nt % NNODES;
    float sc = __ldg(&g_scale[n]), sh = __ldg(&g_shift[n]);
    const float* p = &g_c3[(size_t)nt * 6];
    float v[6];
#pragma unroll
    for (int hh = 0; hh < 6; ++hh) v[hh] = fmaf(p[hh], sc, sh);
#pragma unroll
    for (int j = 0; j < 6; ++j) {
        float o = s_bl[j];
#pragma unroll
        for (int hh = 0; hh < 6; ++hh) o = fmaf(v[hh], s_wl[j * 6 + hh], o);
        out[nt * 6 + j] = o;
    }
}

// ---------------- launch ----------------------------------------------------
extern "C" void kernel_launch(void* const* d_in, const int* in_sizes, int n_in,
                              void* d_out, int out_size) {
    const float* X    = (const float*)d_in[1];
    const float* Wih  = (const float*)d_in[3];
    const float* Whh  = (const float*)d_in[4];
    const float* bih  = (const float*)d_in[5];
    const float* bhh  = (const float*)d_in[6];
    const float* Wc1  = (const float*)d_in[7];
    const float* bc1  = (const float*)d_in[8];
    const float* Wc2  = (const float*)d_in[9];
    const float* bc2  = (const float*)d_in[10];
    const float* Wc3  = (const float*)d_in[11];
    const float* bc3  = (const float*)d_in[12];
    const float* gamma = (const float*)d_in[13];
    const float* beta  = (const float*)d_in[14];
    const float* Wl   = (const float*)d_in[15];
    const float* bl   = (const float*)d_in[16];
    float* out = (float*)d_out;

    unsigned short *r1h, *r1l, *r2h, *r2l, *r3h, *r3l;
    unsigned int *b1, *b2, *b3;
    float* c3;
    cudaGetSymbolAddress((void**)&r1h, g_R1h);
    cudaGetSymbolAddress((void**)&r1l, g_R1l);
    cudaGetSymbolAddress((void**)&r2h, g_R2h);
    cudaGetSymbolAddress((void**)&r2l, g_R2l);
    cudaGetSymbolAddress((void**)&r3h, g_R3h);
    cudaGetSymbolAddress((void**)&r3l, g_R3l);
    cudaGetSymbolAddress((void**)&b1, g_B1);
    cudaGetSymbolAddress((void**)&b2, g_B2);
    cudaGetSymbolAddress((void**)&b3, g_B3);
    cudaGetSymbolAddress((void**)&c3, g_c3);

    cudaFuncSetAttribute(conv_mma<K1, 194, 26, K23, false>,
                         cudaFuncAttributeMaxDynamicSharedMemorySize, CONV_SMEM_B);
    cudaFuncSetAttribute(conv_mma<K23, 194, 26, K23, false>,
                         cudaFuncAttributeMaxDynamicSharedMemorySize, CONV_SMEM_B);
    cudaFuncSetAttribute(conv_mma<K23, 97, 13, K23, true>,
                         cudaFuncAttributeMaxDynamicSharedMemorySize, CONV_SMEM_B);

    const int NPACK = (7 * 26 + 13 * 26 + 13 * 13) * 192;
    pack_B<<<(NPACK + 255) / 256, 256>>>(Wc1, Wc2, Wc3);
    lstm_kernel<<<dim3(NCHUNK, 4), 160>>>(X, Wih, bih, bhh, Whh, r1h, r1l);
    conv_mma<K1, 194, 26, K23, false>
        <<<dim3(1024, 2), 256, CONV_SMEM_B>>>(r1h, r1l, b1, bc1, r2h, r2l, nullptr);
    conv_mma<K23, 194, 26, K23, false>
        <<<dim3(1024, 2), 256, CONV_SMEM_B>>>(r2h, r2l, b2, bc2, r3h, r3l, nullptr);
    conv_mma<K23, 97, 13, K23, true>
        <<<dim3(1024, 1), 256, CONV_SMEM_B>>>(r3h, r3l, b3, bc3, nullptr, nullptr, c3);
    bnstats_kernel<<<97, 256>>>(gamma, beta);
    final_kernel<<<(T_STEPS * NNODES + 255) / 256, 256>>>(Wl, bl, out);
}